// round 1
// baseline (speedup 1.0000x reference)
#include <cuda_runtime.h>
#include <cstdint>

#define CIN      64
#define COUT     64
#define BATCH    16
#define IM       32
#define LOCS     1024      // 32*32 output locations
#define KVOL     576       // CIN * 3 * 3  (reduction length)
#define PSTR     20        // patch smem row stride in floats (80B: 16B-aligned, conflict-friendly)
#define OSTRIDE  589824    // LOCS * KVOL : weight stride between output channels (elements)

// ---------------- scratch (static device globals; no allocation) ----------------
__device__ float g_y[LOCS * 1024];      // conv+bias result, layout [loc][b*64+o] (CTA-coalesced)
__device__ float g_psum[LOCS * COUT];   // per-location per-channel partial sum   (deterministic)
__device__ float g_psumsq[LOCS * COUT]; // per-location per-channel partial sumsq
__device__ float g_scale[COUT];
__device__ float g_shift[COUT];

// ---------------- f32x2 helpers (Blackwell FFMA2 path) ----------------
__device__ __forceinline__ unsigned long long pk2(float lo, float hi) {
    unsigned long long r;
    asm("mov.b64 %0, {%1, %2};" : "=l"(r)
        : "r"(__float_as_uint(lo)), "r"(__float_as_uint(hi)));
    return r;
}
__device__ __forceinline__ float2 upk(unsigned long long v) {
    unsigned u0, u1;
    asm("mov.b64 {%0, %1}, %2;" : "=r"(u0), "=r"(u1) : "l"(v));
    return make_float2(__uint_as_float(u0), __uint_as_float(u1));
}
__device__ __forceinline__ void fma2(unsigned long long& d, unsigned long long a,
                                     unsigned long long b) {
    asm("fma.rn.f32x2 %0, %1, %2, %0;" : "+l"(d) : "l"(a), "l"(b));
}

// ---------------- kernel 1: locally-connected conv + bias + partial stats ----------------
// One CTA per output location. 512 threads = 16 warps; warp w owns output channels
// [4w, 4w+4). Lanes split K 32 ways -> every weight load is one coalesced 128B line,
// each weight element touched exactly once from DRAM.
__global__ __launch_bounds__(512, 1)
void conv_kernel(const float* __restrict__ x, const float* __restrict__ w,
                 const float* __restrict__ bias) {
    __shared__ float ps[KVOL * PSTR];   // 46080 B: patches transposed [k][b], padded rows

    const int tid = threadIdx.x;
    const int loc = blockIdx.x;
    const int i0 = loc >> 5, j0 = loc & 31;

    // Phase 1: build patch matrix ps[k*PSTR + b], k = c*9 + p*3 + q (matches weight layout)
    for (int idx = tid; idx < KVOL * BATCH; idx += 512) {
        int k = idx >> 4, b = idx & 15;
        int c = k / 9, r = k - c * 9;
        int p = r / 3, q = r - p * 3;
        int ii = i0 + p - 1, jj = j0 + q - 1;
        float v = 0.0f;
        if ((unsigned)ii < 32u && (unsigned)jj < 32u)
            v = x[((b * CIN + c) * IM + ii) * IM + jj];
        ps[k * PSTR + b] = v;
    }
    __syncthreads();

    const int lane = tid & 31;
    const int wid  = tid >> 5;
    const int ob   = wid * 4;                       // first o of this warp's quad
    const float* wp = w + (size_t)ob * OSTRIDE + (size_t)loc * KVOL;

    // 32 packed accumulators: acc[oo*8 + bp] holds (y[b=2bp], y[b=2bp+1]) partial for o=ob+oo
    unsigned long long acc[32];
#pragma unroll
    for (int v = 0; v < 32; v++) acc[v] = 0ULL;

    // prefetch first weight quad
    float wc[4];
#pragma unroll
    for (int oo = 0; oo < 4; oo++) wc[oo] = wp[oo * OSTRIDE + lane];

#pragma unroll
    for (int kk = 0; kk < 18; kk++) {               // 18 * 32 = 576 = KVOL exactly
        float wn[4];
        if (kk < 17) {
            const int kn = (kk + 1) * 32 + lane;
#pragma unroll
            for (int oo = 0; oo < 4; oo++) wn[oo] = wp[oo * OSTRIDE + kn];
        }
        // 16 patch values for this lane's k, as 8 packed f32x2 (4x LDS.128, 16B-aligned)
        const float* pr = &ps[(kk * 32 + lane) * PSTR];
        unsigned long long pb[8];
#pragma unroll
        for (int h = 0; h < 4; h++) {
            ulonglong2 u = *(const ulonglong2*)(pr + h * 4);
            pb[h * 2] = u.x;
            pb[h * 2 + 1] = u.y;
        }
#pragma unroll
        for (int oo = 0; oo < 4; oo++) {
            unsigned long long wd = pk2(wc[oo], wc[oo]);
#pragma unroll
            for (int bp = 0; bp < 8; bp++)
                fma2(acc[oo * 8 + bp], wd, pb[bp]);
        }
        if (kk < 17) {
#pragma unroll
            for (int oo = 0; oo < 4; oo++) wc[oo] = wn[oo];
        }
    }

    // Split-butterfly cross-lane reduction: 31 packed exchanges; lane L ends holding
    // the fully-reduced acc for (oo = L>>3, bp = L&7).
#pragma unroll
    for (int off = 16; off >= 1; off >>= 1) {
        const bool up = (lane & off) != 0;
#pragma unroll
        for (int v = 0; v < off; v++) {
            unsigned long long give = up ? acc[v] : acc[v + off];
            unsigned long long keep = up ? acc[v + off] : acc[v];
            float2 g = upk(give);
            g.x = __shfl_xor_sync(0xffffffffu, g.x, off);
            g.y = __shfl_xor_sync(0xffffffffu, g.y, off);
            float2 kf = upk(keep);
            acc[v] = pk2(kf.x + g.x, kf.y + g.y);
        }
    }

    const int oo = lane >> 3, bp = lane & 7;
    const int o = ob + oo;
    const float bz = bias[o * LOCS + loc];
    float2 yv = upk(acc[0]);
    const float y0 = yv.x + bz;
    const float y1 = yv.y + bz;

    // per-channel (8-lane group) partial stats — deterministic shfl tree, no float atomics
    float s  = y0 + y1;
    float q2 = y0 * y0 + y1 * y1;
#pragma unroll
    for (int off = 4; off >= 1; off >>= 1) {
        s  += __shfl_xor_sync(0xffffffffu, s, off);
        q2 += __shfl_xor_sync(0xffffffffu, q2, off);
    }
    if (bp == 0) {
        g_psum[loc * COUT + o]   = s;
        g_psumsq[loc * COUT + o] = q2;
    }

    // Stage outputs in smem, then one coalesced 4KB store per CTA
    __syncthreads();                 // everyone done reading ps
    float* buf = ps;                 // reuse patch smem
    buf[(bp * 2) * COUT + o]     = y0;
    buf[(bp * 2 + 1) * COUT + o] = y1;
    __syncthreads();
    if (tid < 256) {
        float4* dst = (float4*)&g_y[loc * 1024];
        const float4* src = (const float4*)buf;
        dst[tid] = src[tid];
    }
}

// ---------------- kernel 2: finalize batch statistics (deterministic tree) ----------------
__global__ __launch_bounds__(256)
void stats_kernel(const float* __restrict__ gamma, const float* __restrict__ beta) {
    __shared__ float ss[256], sq[256];
    const int o = blockIdx.x, t = threadIdx.x;
    float s = 0.0f, q = 0.0f;
    for (int l = t; l < LOCS; l += 256) {
        s += g_psum[l * COUT + o];
        q += g_psumsq[l * COUT + o];
    }
    ss[t] = s; sq[t] = q;
    __syncthreads();
#pragma unroll
    for (int h = 128; h >= 1; h >>= 1) {
        if (t < h) { ss[t] += ss[t + h]; sq[t] += sq[t + h]; }
        __syncthreads();
    }
    if (t == 0) {
        const float N = (float)(BATCH * LOCS);
        float mean = ss[0] / N;
        float var  = sq[0] / N - mean * mean;
        float sc   = gamma[o] * rsqrtf(var + 1e-5f);
        g_scale[o] = sc;
        g_shift[o] = beta[o] - mean * sc;
    }
}

// ---------------- kernel 3: tiled transpose + BN affine + ReLU ----------------
// g_y is [loc][bo]; output is [bo][loc]. 32x32 smem tile keeps both sides coalesced.
__global__ __launch_bounds__(256)
void bn_kernel(float* __restrict__ out) {
    __shared__ float tile[32][33];
    __shared__ float s_sc[32], s_sh[32];
    const int t = threadIdx.x;
    const int tx = blockIdx.x;   // bo tile index
    const int ty = blockIdx.y;   // loc tile index
    if (t < 32) {
        int o = (tx * 32 + t) & 63;
        s_sc[t] = g_scale[o];
        s_sh[t] = g_shift[o];
    }
    const int lr = t >> 5;   // 0..7
    const int lc = t & 31;
#pragma unroll
    for (int p = 0; p < 4; p++) {
        int r = p * 8 + lr;  // loc-local row
        tile[r][lc] = g_y[(ty * 32 + r) * 1024 + tx * 32 + lc];
    }
    __syncthreads();
#pragma unroll
    for (int p = 0; p < 4; p++) {
        int r = p * 8 + lr;          // bo-local
        int bo  = tx * 32 + r;
        int loc = ty * 32 + lc;
        float v = tile[lc][r] * s_sc[r] + s_sh[r];
        out[bo * 1024 + loc] = fmaxf(v, 0.0f);
    }
}

// ---------------- launch ----------------
extern "C" void kernel_launch(void* const* d_in, const int* in_sizes, int n_in,
                              void* d_out, int out_size) {
    const float* x     = (const float*)d_in[0];
    const float* w     = (const float*)d_in[1];
    const float* bias  = (const float*)d_in[2];
    const float* gamma = (const float*)d_in[3];
    const float* beta  = (const float*)d_in[4];
    float* out = (float*)d_out;

    conv_kernel<<<LOCS, 512>>>(x, w, bias);
    stats_kernel<<<COUT, 256>>>(gamma, beta);
    bn_kernel<<<dim3(32, 32), 256>>>(out);
}

// round 2
// speedup vs baseline: 1.0640x; 1.0640x over previous
#include <cuda_runtime.h>
#include <cstdint>

#define CIN      64
#define COUT     64
#define BATCH    16
#define IM       32
#define LOCS     1024      // 32*32 output locations
#define KVOL     576       // CIN * 3 * 3  (reduction length)
#define PSTR     20        // patch smem row stride in floats (80B: 16B-aligned, conflict-free)
#define OSTRIDE  589824    // LOCS * KVOL : weight stride between output channels (elements)

// ---------------- scratch (static device globals; no allocation) ----------------
__device__ float g_y[LOCS * 1024];      // conv+bias result, layout [loc][b*64+o]
__device__ float g_psum[LOCS * COUT];
__device__ float g_psumsq[LOCS * COUT];
__device__ float g_scale[COUT];
__device__ float g_shift[COUT];

// ---------------- f32x2 helpers (Blackwell FFMA2 path) ----------------
__device__ __forceinline__ unsigned long long pk2(float lo, float hi) {
    unsigned long long r;
    asm("mov.b64 %0, {%1, %2};" : "=l"(r)
        : "r"(__float_as_uint(lo)), "r"(__float_as_uint(hi)));
    return r;
}
__device__ __forceinline__ float2 upk(unsigned long long v) {
    unsigned u0, u1;
    asm("mov.b64 {%0, %1}, %2;" : "=r"(u0), "=r"(u1) : "l"(v));
    return make_float2(__uint_as_float(u0), __uint_as_float(u1));
}
__device__ __forceinline__ void fma2(unsigned long long& d, unsigned long long a,
                                     unsigned long long b) {
    asm("fma.rn.f32x2 %0, %1, %2, %0;" : "+l"(d) : "l"(a), "l"(b));
}

// Physical patch-row swizzle: lane owns 4 consecutive k (vector weight loads) but
// reads smem with lane-stride of ONE physical row (conflict-free with PSTR=20).
//   main blocks (k < 512):  k = blk*128 + 4L + j  ->  phys = blk*128 + (j<<5) + L
//   tail        (k >= 512): k = 512 + 2L + j      ->  phys = 512 + (j<<5) + L
__device__ __forceinline__ int sigma(int k) {
    if (k < 512) return (k & ~127) | ((k & 3) << 5) | ((k >> 2) & 31);
    return 512 + ((k & 1) << 5) + ((k >> 1) & 31);
}

// ---------------- kernel 1: locally-connected conv + bias + partial stats ----------------
__global__ __launch_bounds__(512, 1)
void conv_kernel(const float* __restrict__ x, const float* __restrict__ w,
                 const float* __restrict__ bias) {
    __shared__ float ps[KVOL * PSTR];   // 46080 B: patches [phys_row][b]

    const int tid = threadIdx.x;
    const int loc = blockIdx.x;
    const int i0 = loc >> 5, j0 = loc & 31;

    // Phase 1: stage patches; logical k = c*9 + p*3 + q placed at physical row sigma(k)
    for (int idx = tid; idx < KVOL * BATCH; idx += 512) {
        int k = idx >> 4, b = idx & 15;
        int c = k / 9, r = k - c * 9;
        int p = r / 3, q = r - p * 3;
        int ii = i0 + p - 1, jj = j0 + q - 1;
        float v = 0.0f;
        if ((unsigned)ii < 32u && (unsigned)jj < 32u)
            v = x[((b * CIN + c) * IM + ii) * IM + jj];
        ps[sigma(k) * PSTR + b] = v;
    }
    __syncthreads();

    const int lane = tid & 31;
    const int wid  = tid >> 5;
    const int ob   = wid * 4;                       // this warp's o-quad
    const float* wp = w + (size_t)ob * OSTRIDE + (size_t)loc * KVOL;

    unsigned long long acc[32];                     // acc[oo*8+bp] = (y[2bp], y[2bp+1]) for o=ob+oo
#pragma unroll
    for (int v = 0; v < 32; v++) acc[v] = 0ULL;

    // Vectorized weights: lane owns k = blk*128 + lane*4 + j  -> LDG.128 per (o,blk)
    float4 wc[4], wn[4];
    float2 wt[4];
#pragma unroll
    for (int oo = 0; oo < 4; oo++)
        wc[oo] = *(const float4*)(wp + (size_t)oo * OSTRIDE + lane * 4);

#pragma unroll
    for (int blk = 0; blk < 4; blk++) {
        if (blk < 3) {
#pragma unroll
            for (int oo = 0; oo < 4; oo++)
                wn[oo] = *(const float4*)(wp + (size_t)oo * OSTRIDE + (blk + 1) * 128 + lane * 4);
        } else {
#pragma unroll
            for (int oo = 0; oo < 4; oo++)
                wt[oo] = *(const float2*)(wp + (size_t)oo * OSTRIDE + 512 + lane * 2);
        }
#pragma unroll
        for (int j = 0; j < 4; j++) {
            const float* pr = &ps[(blk * 128 + (j << 5) + lane) * PSTR];
            unsigned long long pb[8];
#pragma unroll
            for (int h = 0; h < 4; h++) {
                ulonglong2 u = *(const ulonglong2*)(pr + h * 4);
                pb[h * 2] = u.x;
                pb[h * 2 + 1] = u.y;
            }
#pragma unroll
            for (int oo = 0; oo < 4; oo++) {
                float wv = (j == 0) ? wc[oo].x : (j == 1) ? wc[oo].y
                         : (j == 2) ? wc[oo].z : wc[oo].w;
                unsigned long long wd = pk2(wv, wv);
#pragma unroll
                for (int bp = 0; bp < 8; bp++)
                    fma2(acc[oo * 8 + bp], wd, pb[bp]);
            }
        }
        if (blk < 3) {
#pragma unroll
            for (int oo = 0; oo < 4; oo++) wc[oo] = wn[oo];
        }
    }
    // tail: k = 512 + lane*2 + j, j in {0,1}
#pragma unroll
    for (int j = 0; j < 2; j++) {
        const float* pr = &ps[(512 + (j << 5) + lane) * PSTR];
        unsigned long long pb[8];
#pragma unroll
        for (int h = 0; h < 4; h++) {
            ulonglong2 u = *(const ulonglong2*)(pr + h * 4);
            pb[h * 2] = u.x;
            pb[h * 2 + 1] = u.y;
        }
#pragma unroll
        for (int oo = 0; oo < 4; oo++) {
            float wv = j ? wt[oo].y : wt[oo].x;
            unsigned long long wd = pk2(wv, wv);
#pragma unroll
            for (int bp = 0; bp < 8; bp++)
                fma2(acc[oo * 8 + bp], wd, pb[bp]);
        }
    }

    // Split-butterfly cross-lane reduction: lane L ends with acc for (oo=L>>3, bp=L&7)
#pragma unroll
    for (int off = 16; off >= 1; off >>= 1) {
        const bool up = (lane & off) != 0;
#pragma unroll
        for (int v = 0; v < off; v++) {
            unsigned long long give = up ? acc[v] : acc[v + off];
            unsigned long long keep = up ? acc[v + off] : acc[v];
            float2 g = upk(give);
            g.x = __shfl_xor_sync(0xffffffffu, g.x, off);
            g.y = __shfl_xor_sync(0xffffffffu, g.y, off);
            float2 kf = upk(keep);
            acc[v] = pk2(kf.x + g.x, kf.y + g.y);
        }
    }

    const int oo = lane >> 3, bp = lane & 7;
    const int o = ob + oo;
    const float bz = bias[o * LOCS + loc];
    float2 yv = upk(acc[0]);
    const float y0 = yv.x + bz;
    const float y1 = yv.y + bz;

    // per-channel partial stats (deterministic shfl tree)
    float s  = y0 + y1;
    float q2 = y0 * y0 + y1 * y1;
#pragma unroll
    for (int off = 4; off >= 1; off >>= 1) {
        s  += __shfl_xor_sync(0xffffffffu, s, off);
        q2 += __shfl_xor_sync(0xffffffffu, q2, off);
    }
    if (bp == 0) {
        g_psum[loc * COUT + o]   = s;
        g_psumsq[loc * COUT + o] = q2;
    }

    // stage outputs in smem, one coalesced 4KB store
    __syncthreads();
    float* buf = ps;
    buf[(bp * 2) * COUT + o]     = y0;
    buf[(bp * 2 + 1) * COUT + o] = y1;
    __syncthreads();
    if (tid < 256) {
        float4* dst = (float4*)&g_y[loc * 1024];
        const float4* src = (const float4*)buf;
        dst[tid] = src[tid];
    }
}

// ---------------- kernel 2: finalize batch statistics ----------------
__global__ __launch_bounds__(256)
void stats_kernel(const float* __restrict__ gamma, const float* __restrict__ beta) {
    __shared__ float ss[256], sq[256];
    const int o = blockIdx.x, t = threadIdx.x;
    float s = 0.0f, q = 0.0f;
    for (int l = t; l < LOCS; l += 256) {
        s += g_psum[l * COUT + o];
        q += g_psumsq[l * COUT + o];
    }
    ss[t] = s; sq[t] = q;
    __syncthreads();
#pragma unroll
    for (int h = 128; h >= 1; h >>= 1) {
        if (t < h) { ss[t] += ss[t + h]; sq[t] += sq[t + h]; }
        __syncthreads();
    }
    if (t == 0) {
        const float N = (float)(BATCH * LOCS);
        float mean = ss[0] / N;
        float var  = sq[0] / N - mean * mean;
        float sc   = gamma[o] * rsqrtf(var + 1e-5f);
        g_scale[o] = sc;
        g_shift[o] = beta[o] - mean * sc;
    }
}

// ---------------- kernel 3: tiled transpose + BN affine + ReLU ----------------
__global__ __launch_bounds__(256)
void bn_kernel(float* __restrict__ out) {
    __shared__ float tile[32][33];
    __shared__ float s_sc[32], s_sh[32];
    const int t = threadIdx.x;
    const int tx = blockIdx.x;   // bo tile
    const int ty = blockIdx.y;   // loc tile
    if (t < 32) {
        int o = (tx * 32 + t) & 63;
        s_sc[t] = g_scale[o];
        s_sh[t] = g_shift[o];
    }
    const int lr = t >> 5;
    const int lc = t & 31;
#pragma unroll
    for (int p = 0; p < 4; p++) {
        int r = p * 8 + lr;
        tile[r][lc] = g_y[(ty * 32 + r) * 1024 + tx * 32 + lc];
    }
    __syncthreads();
#pragma unroll
    for (int p = 0; p < 4; p++) {
        int r = p * 8 + lr;
        int bo  = tx * 32 + r;
        int loc = ty * 32 + lc;
        float v = tile[lc][r] * s_sc[r] + s_sh[r];
        out[bo * 1024 + loc] = fmaxf(v, 0.0f);
    }
}

// ---------------- launch ----------------
extern "C" void kernel_launch(void* const* d_in, const int* in_sizes, int n_in,
                              void* d_out, int out_size) {
    const float* x     = (const float*)d_in[0];
    const float* w     = (const float*)d_in[1];
    const float* bias  = (const float*)d_in[2];
    const float* gamma = (const float*)d_in[3];
    const float* beta  = (const float*)d_in[4];
    float* out = (float*)d_out;

    conv_kernel<<<LOCS, 512>>>(x, w, bias);
    stats_kernel<<<COUT, 256>>>(gamma, beta);
    bn_kernel<<<dim3(32, 32), 256>>>(out);
}